// round 1
// baseline (speedup 1.0000x reference)
#include <cuda_runtime.h>
#include <math.h>

// Problem dims
#define NB 1024   // batch
#define NT 64     // time steps
#define NV 1024   // vocab
#define NE 512    // embed dim
#define NM 1024   // modes
#define NL 32     // MZI layers
#define NPE 512   // even pairs
#define NPO 511   // odd pairs
#define G3E 1536  // 3*NE

// Scratch (no allocations allowed -> __device__ globals)
__device__ float g_G[NV * G3E];       // precomputed input gates per token: embed@W_ih^T + b_ih
__device__ float g_h[2][NB * NE];     // GRU hidden double buffer
__device__ float g_zc[NB * 2 * NM];   // h@Wc^T + bc
__device__ float g_pr[NB * NM];       // psi real
__device__ float g_pi[NB * NM];       // psi imag

// ---------------------------------------------------------------------------
// Generic tiled GEMM: C[Mr x Nc] = A[Mr x K] * Bm[Nc x K]^T + bias[Nc]
// BM=BN=64, BK=16, 256 threads, 4x4 per-thread microtile. Dims must be
// multiples of 64/16 (they are: 1024/1536/2048 x 512).
// ---------------------------------------------------------------------------
__global__ __launch_bounds__(256) void gemm64_abT(
    const float* __restrict__ A, const float* __restrict__ Bm,
    const float* __restrict__ bias, float* __restrict__ C, int Nc, int K)
{
    __shared__ float As[64][17];
    __shared__ float Bs[16][65];
    int tid = threadIdx.x;
    int r4 = tid >> 2, q = tid & 3;      // loader mapping
    int ty = tid >> 4, tx = tid & 15;    // compute mapping
    int rb = blockIdx.y * 64, cb = blockIdx.x * 64;

    float acc[4][4];
#pragma unroll
    for (int i = 0; i < 4; i++)
#pragma unroll
        for (int j = 0; j < 4; j++) acc[i][j] = 0.f;

    for (int k0 = 0; k0 < K; k0 += 16) {
        float4 av = *(const float4*)(A + (size_t)(rb + r4) * K + k0 + q * 4);
        As[r4][q * 4 + 0] = av.x; As[r4][q * 4 + 1] = av.y;
        As[r4][q * 4 + 2] = av.z; As[r4][q * 4 + 3] = av.w;
        float4 bv = *(const float4*)(Bm + (size_t)(cb + r4) * K + k0 + q * 4);
        Bs[q * 4 + 0][r4] = bv.x; Bs[q * 4 + 1][r4] = bv.y;
        Bs[q * 4 + 2][r4] = bv.z; Bs[q * 4 + 3][r4] = bv.w;
        __syncthreads();
#pragma unroll
        for (int kk = 0; kk < 16; kk++) {
            float a[4], b[4];
#pragma unroll
            for (int i = 0; i < 4; i++) a[i] = As[ty * 4 + i][kk];
#pragma unroll
            for (int j = 0; j < 4; j++) b[j] = Bs[kk][tx * 4 + j];
#pragma unroll
            for (int i = 0; i < 4; i++)
#pragma unroll
                for (int j = 0; j < 4; j++) acc[i][j] = fmaf(a[i], b[j], acc[i][j]);
        }
        __syncthreads();
    }
#pragma unroll
    for (int i = 0; i < 4; i++) {
        int row = rb + ty * 4 + i;
#pragma unroll
        for (int j = 0; j < 4; j++) {
            int col = cb + tx * 4 + j;
            C[(size_t)row * Nc + col] = acc[i][j] + bias[col];
        }
    }
}

// ---------------------------------------------------------------------------
// Fused GRU step: computes Hg = h@W_hh^T (3 gates share the A tile), gathers
// precomputed input gates from g_G by token, applies gate math, writes h_out.
// Grid: (NE/64, NB/64). One launch per timestep.
// ---------------------------------------------------------------------------
__global__ __launch_bounds__(256) void gru_step(
    const float* __restrict__ hin, float* __restrict__ hout,
    const float* __restrict__ W_hh, const float* __restrict__ b_hh,
    const int* __restrict__ tokens, int t)
{
    __shared__ float As[64][17];
    __shared__ float Bs[3][16][65];
    int tid = threadIdx.x;
    int r4 = tid >> 2, q = tid & 3;
    int ty = tid >> 4, tx = tid & 15;
    int rb = blockIdx.y * 64, cb = blockIdx.x * 64;

    float acc[3][4][4];
#pragma unroll
    for (int g = 0; g < 3; g++)
#pragma unroll
        for (int i = 0; i < 4; i++)
#pragma unroll
            for (int j = 0; j < 4; j++) acc[g][i][j] = 0.f;

    for (int k0 = 0; k0 < NE; k0 += 16) {
        float4 av = *(const float4*)(hin + (size_t)(rb + r4) * NE + k0 + q * 4);
        As[r4][q * 4 + 0] = av.x; As[r4][q * 4 + 1] = av.y;
        As[r4][q * 4 + 2] = av.z; As[r4][q * 4 + 3] = av.w;
#pragma unroll
        for (int g = 0; g < 3; g++) {
            float4 bv = *(const float4*)(W_hh + (size_t)(g * NE + cb + r4) * NE + k0 + q * 4);
            Bs[g][q * 4 + 0][r4] = bv.x; Bs[g][q * 4 + 1][r4] = bv.y;
            Bs[g][q * 4 + 2][r4] = bv.z; Bs[g][q * 4 + 3][r4] = bv.w;
        }
        __syncthreads();
#pragma unroll
        for (int kk = 0; kk < 16; kk++) {
            float a[4], b[3][4];
#pragma unroll
            for (int i = 0; i < 4; i++) a[i] = As[ty * 4 + i][kk];
#pragma unroll
            for (int g = 0; g < 3; g++)
#pragma unroll
                for (int j = 0; j < 4; j++) b[g][j] = Bs[g][kk][tx * 4 + j];
#pragma unroll
            for (int g = 0; g < 3; g++)
#pragma unroll
                for (int i = 0; i < 4; i++)
#pragma unroll
                    for (int j = 0; j < 4; j++)
                        acc[g][i][j] = fmaf(a[i], b[g][j], acc[g][i][j]);
        }
        __syncthreads();
    }

#pragma unroll
    for (int i = 0; i < 4; i++) {
        int row = rb + ty * 4 + i;
        int tok = tokens[row * NT + t];
        const float* Gr = g_G + (size_t)tok * G3E;
#pragma unroll
        for (int j = 0; j < 4; j++) {
            int col = cb + tx * 4 + j;
            float hr = acc[0][i][j] + b_hh[col];
            float hz = acc[1][i][j] + b_hh[NE + col];
            float hn = acc[2][i][j] + b_hh[2 * NE + col];
            float ir = Gr[col];
            float iz = Gr[NE + col];
            float in_ = Gr[2 * NE + col];
            float r = 1.f / (1.f + expf(-(ir + hr)));
            float z = 1.f / (1.f + expf(-(iz + hz)));
            float n = tanhf(in_ + r * hn);
            float hprev = hin[(size_t)row * NE + col];
            hout[(size_t)row * NE + col] = (1.f - z) * n + z * hprev;
        }
    }
}

__global__ void zero_kernel(float* p, int n)
{
    int i = blockIdx.x * blockDim.x + threadIdx.x;
    if (i < n) p[i] = 0.f;
}

// ---------------------------------------------------------------------------
// psi init: split zc -> (re, im), complex_normalize per row.
// ---------------------------------------------------------------------------
__global__ __launch_bounds__(256) void psi_init_kernel()
{
    int b = blockIdx.x, tid = threadIdx.x;
    __shared__ float red[8];
    const float* zrow = g_zc + (size_t)b * 2 * NM;
    float ss = 0.f;
    for (int m = tid; m < NM; m += 256) {
        float re = zrow[m], im = zrow[NM + m];
        ss += re * re + im * im;
    }
    for (int o = 16; o; o >>= 1) ss += __shfl_xor_sync(0xffffffffu, ss, o);
    if ((tid & 31) == 0) red[tid >> 5] = ss;
    __syncthreads();
    if (tid < 8) {
        float v = red[tid];
        for (int o = 4; o; o >>= 1) v += __shfl_xor_sync(0xffu, v, o);
        if (tid == 0) red[0] = v;
    }
    __syncthreads();
    float inv = 1.f / sqrtf(red[0] + 1e-8f);
    for (int m = tid; m < NM; m += 256) {
        g_pr[(size_t)b * NM + m] = zrow[m] * inv;
        g_pi[(size_t)b * NM + m] = zrow[NM + m] * inv;
    }
}

// ---------------------------------------------------------------------------
// MZI layers: one block per batch row, psi row lives in SMEM for all 32 layers.
// ---------------------------------------------------------------------------
__device__ __forceinline__ void pair_apply(int a, int c, float tt, float pp, float rr,
                                           float* sre, float* sim)
{
    float st, ct; sincosf(tt, &st, &ct);
    float sp, cp; sincosf(pp, &sp, &cp);
    float sr, cr; sincosf(rr, &sr, &cr);
    float cpr = cp * cr - sp * sr;      // cos(p+r)
    float spr = sp * cr + cp * sr;      // sin(p+r)
    float u11r = ct * cpr, u11i = ct * spr;   // e^{ip} c e^{ir}
    float u12r = -st * sp, u12i = st * cp;    // e^{ip} * i s
    float u21r = -st * sr, u21i = st * cr;    // i s * e^{ir}
    float u22  = ct;                          // real
    float v0r = sre[a], v0i = sim[a], v1r = sre[c], v1i = sim[c];
    float n0r = u11r * v0r - u11i * v0i + u12r * v1r - u12i * v1i;
    float n0i = u11r * v0i + u11i * v0r + u12r * v1i + u12i * v1r;
    float n1r = u21r * v0r - u21i * v0i + u22 * v1r;
    float n1i = u21r * v0i + u21i * v0r + u22 * v1i;
    sre[a] = n0r; sim[a] = n0i; sre[c] = n1r; sim[c] = n1i;
}

__global__ __launch_bounds__(512) void mzi_kernel(
    const float* __restrict__ phase, const float* __restrict__ te,
    const float* __restrict__ pe, const float* __restrict__ re_,
    const float* __restrict__ to, const float* __restrict__ po,
    const float* __restrict__ ro)
{
    __shared__ float sre[NM], sim[NM];
    __shared__ float red[16];
    int b = blockIdx.x, tid = threadIdx.x;
    sre[tid] = g_pr[(size_t)b * NM + tid];
    sre[tid + 512] = g_pr[(size_t)b * NM + tid + 512];
    sim[tid] = g_pi[(size_t)b * NM + tid];
    sim[tid + 512] = g_pi[(size_t)b * NM + tid + 512];
    __syncthreads();

    for (int l = 0; l < NL; l++) {
        // phase rotation
#pragma unroll
        for (int h = 0; h < 2; h++) {
            int mm = tid + h * 512;
            float s, c; sincosf(phase[l * NM + mm], &s, &c);
            float r0 = sre[mm], i0 = sim[mm];
            sre[mm] = r0 * c - i0 * s;
            sim[mm] = r0 * s + i0 * c;
        }
        __syncthreads();
        // even pairs (2p, 2p+1)
        pair_apply(2 * tid, 2 * tid + 1,
                   te[l * NPE + tid], pe[l * NPE + tid], re_[l * NPE + tid], sre, sim);
        __syncthreads();
        // odd pairs (2p+1, 2p+2)
        if (tid < NPO)
            pair_apply(2 * tid + 1, 2 * tid + 2,
                       to[l * NPO + tid], po[l * NPO + tid], ro[l * NPO + tid], sre, sim);
        __syncthreads();
        // normalize
        float ss = sre[tid] * sre[tid] + sim[tid] * sim[tid]
                 + sre[tid + 512] * sre[tid + 512] + sim[tid + 512] * sim[tid + 512];
        for (int o = 16; o; o >>= 1) ss += __shfl_xor_sync(0xffffffffu, ss, o);
        if ((tid & 31) == 0) red[tid >> 5] = ss;
        __syncthreads();
        if (tid < 16) {
            float v = red[tid];
            for (int o = 8; o; o >>= 1) v += __shfl_xor_sync(0xffffu, v, o);
            if (tid == 0) red[0] = v;
        }
        __syncthreads();
        float inv = 1.f / sqrtf(red[0] + 1e-8f);
        sre[tid] *= inv; sim[tid] *= inv;
        sre[tid + 512] *= inv; sim[tid + 512] *= inv;
        __syncthreads();
    }

    g_pr[(size_t)b * NM + tid] = sre[tid];
    g_pr[(size_t)b * NM + tid + 512] = sre[tid + 512];
    g_pi[(size_t)b * NM + tid] = sim[tid];
    g_pi[(size_t)b * NM + tid + 512] = sim[tid + 512];
}

// ---------------------------------------------------------------------------
// Readout: amps = psi @ R^T (complex), out = log(|amps|^2 + 1e-12).
// Tiled complex GEMM, 64x64x16, 256 threads, 4x4 per thread (re+im accs).
// ---------------------------------------------------------------------------
__global__ __launch_bounds__(256) void readout_kernel(
    const float* __restrict__ Rr, const float* __restrict__ Ri,
    float* __restrict__ out)
{
    __shared__ float Ar[64][17], Ai[64][17];
    __shared__ float Br[16][65], Bi[16][65];
    int tid = threadIdx.x;
    int r4 = tid >> 2, q = tid & 3;
    int ty = tid >> 4, tx = tid & 15;
    int rb = blockIdx.y * 64, cb = blockIdx.x * 64;

    float accr[4][4], acci[4][4];
#pragma unroll
    for (int i = 0; i < 4; i++)
#pragma unroll
        for (int j = 0; j < 4; j++) { accr[i][j] = 0.f; acci[i][j] = 0.f; }

    for (int k0 = 0; k0 < NM; k0 += 16) {
        float4 v;
        v = *(const float4*)(g_pr + (size_t)(rb + r4) * NM + k0 + q * 4);
        Ar[r4][q * 4 + 0] = v.x; Ar[r4][q * 4 + 1] = v.y;
        Ar[r4][q * 4 + 2] = v.z; Ar[r4][q * 4 + 3] = v.w;
        v = *(const float4*)(g_pi + (size_t)(rb + r4) * NM + k0 + q * 4);
        Ai[r4][q * 4 + 0] = v.x; Ai[r4][q * 4 + 1] = v.y;
        Ai[r4][q * 4 + 2] = v.z; Ai[r4][q * 4 + 3] = v.w;
        v = *(const float4*)(Rr + (size_t)(cb + r4) * NM + k0 + q * 4);
        Br[q * 4 + 0][r4] = v.x; Br[q * 4 + 1][r4] = v.y;
        Br[q * 4 + 2][r4] = v.z; Br[q * 4 + 3][r4] = v.w;
        v = *(const float4*)(Ri + (size_t)(cb + r4) * NM + k0 + q * 4);
        Bi[q * 4 + 0][r4] = v.x; Bi[q * 4 + 1][r4] = v.y;
        Bi[q * 4 + 2][r4] = v.z; Bi[q * 4 + 3][r4] = v.w;
        __syncthreads();
#pragma unroll
        for (int kk = 0; kk < 16; kk++) {
            float par[4], pai[4], wbr[4], wbi[4];
#pragma unroll
            for (int i = 0; i < 4; i++) { par[i] = Ar[ty * 4 + i][kk]; pai[i] = Ai[ty * 4 + i][kk]; }
#pragma unroll
            for (int j = 0; j < 4; j++) { wbr[j] = Br[kk][tx * 4 + j]; wbi[j] = Bi[kk][tx * 4 + j]; }
#pragma unroll
            for (int i = 0; i < 4; i++)
#pragma unroll
                for (int j = 0; j < 4; j++) {
                    accr[i][j] = fmaf(par[i], wbr[j], accr[i][j]);
                    accr[i][j] = fmaf(-pai[i], wbi[j], accr[i][j]);
                    acci[i][j] = fmaf(par[i], wbi[j], acci[i][j]);
                    acci[i][j] = fmaf(pai[i], wbr[j], acci[i][j]);
                }
        }
        __syncthreads();
    }
#pragma unroll
    for (int i = 0; i < 4; i++) {
        int row = rb + ty * 4 + i;
#pragma unroll
        for (int j = 0; j < 4; j++) {
            int col = cb + tx * 4 + j;
            float ar = accr[i][j], ai = acci[i][j];
            out[(size_t)row * NV + col] = logf(ar * ar + ai * ai + 1e-12f);
        }
    }
}

// ---------------------------------------------------------------------------
// Row-wise logsumexp, subtract in place.
// ---------------------------------------------------------------------------
__global__ __launch_bounds__(256) void lse_kernel(float* __restrict__ out)
{
    int b = blockIdx.x, tid = threadIdx.x;
    __shared__ float red[8];
    float* row = out + (size_t)b * NV;

    float mx = -INFINITY;
    for (int v = tid; v < NV; v += 256) mx = fmaxf(mx, row[v]);
    for (int o = 16; o; o >>= 1) mx = fmaxf(mx, __shfl_xor_sync(0xffffffffu, mx, o));
    if ((tid & 31) == 0) red[tid >> 5] = mx;
    __syncthreads();
    if (tid < 8) {
        float v = red[tid];
        for (int o = 4; o; o >>= 1) v = fmaxf(v, __shfl_xor_sync(0xffu, v, o));
        if (tid == 0) red[0] = v;
    }
    __syncthreads();
    mx = red[0];
    __syncthreads();

    float se = 0.f;
    for (int v = tid; v < NV; v += 256) se += expf(row[v] - mx);
    for (int o = 16; o; o >>= 1) se += __shfl_xor_sync(0xffffffffu, se, o);
    if ((tid & 31) == 0) red[tid >> 5] = se;
    __syncthreads();
    if (tid < 8) {
        float v = red[tid];
        for (int o = 4; o; o >>= 1) v += __shfl_xor_sync(0xffu, v, o);
        if (tid == 0) red[0] = v;
    }
    __syncthreads();
    float lse = mx + logf(red[0]);
    for (int v = tid; v < NV; v += 256) row[v] -= lse;
}

// ---------------------------------------------------------------------------
extern "C" void kernel_launch(void* const* d_in, const int* in_sizes, int n_in,
                              void* d_out, int out_size)
{
    const int*   tokens = (const int*)d_in[0];
    const float* embed  = (const float*)d_in[1];
    const float* W_ih   = (const float*)d_in[2];
    const float* W_hh   = (const float*)d_in[3];
    const float* b_ih   = (const float*)d_in[4];
    const float* b_hh   = (const float*)d_in[5];
    const float* Wc     = (const float*)d_in[6];
    const float* bc     = (const float*)d_in[7];
    const float* phase  = (const float*)d_in[8];
    const float* te     = (const float*)d_in[9];
    const float* pe     = (const float*)d_in[10];
    const float* re_    = (const float*)d_in[11];
    const float* to     = (const float*)d_in[12];
    const float* po     = (const float*)d_in[13];
    const float* ro     = (const float*)d_in[14];
    const float* Rr     = (const float*)d_in[15];
    const float* Ri     = (const float*)d_in[16];
    float* out = (float*)d_out;

    static float* pG = nullptr;
    static float* pH = nullptr;
    static float* pZC = nullptr;
    if (!pG) {
        cudaGetSymbolAddress((void**)&pG, g_G);
        cudaGetSymbolAddress((void**)&pH, g_h);
        cudaGetSymbolAddress((void**)&pZC, g_zc);
    }
    float* pH0 = pH;
    float* pH1 = pH + NB * NE;

    // 1. Token gate table: G = embed @ W_ih^T + b_ih  (V x 3E)
    gemm64_abT<<<dim3(G3E / 64, NV / 64), 256>>>(embed, W_ih, b_ih, pG, G3E, NE);

    // 2. h0 = 0
    zero_kernel<<<(NB * NE + 255) / 256, 256>>>(pH0, NB * NE);

    // 3. GRU recurrence, double-buffered (64 steps -> final h in pH0)
    for (int t = 0; t < NT; t++) {
        const float* hin = (t & 1) ? pH1 : pH0;
        float* hout      = (t & 1) ? pH0 : pH1;
        gru_step<<<dim3(NE / 64, NB / 64), 256>>>(hin, hout, W_hh, b_hh, tokens, t);
    }

    // 4. zc = h @ Wc^T + bc  (B x 2M), then normalized complex psi
    gemm64_abT<<<dim3(2 * NM / 64, NB / 64), 256>>>(pH0, Wc, bc, pZC, 2 * NM, NE);
    psi_init_kernel<<<NB, 256>>>();

    // 5. 32 MZI layers, persistent row in SMEM
    mzi_kernel<<<NB, 512>>>(phase, te, pe, re_, to, po, ro);

    // 6. Readout complex GEMM + log|.|^2, then row logsumexp
    readout_kernel<<<dim3(NV / 64, NB / 64), 256>>>(Rr, Ri, out);
    lse_kernel<<<NB, 256>>>(out);
}

// round 3
// speedup vs baseline: 1.7324x; 1.7324x over previous
#include <cuda_runtime.h>
#include <math.h>

// Problem dims
#define NB 1024   // batch
#define NT 64     // time steps
#define NV 1024   // vocab
#define NE 512    // embed dim
#define NM 1024   // modes
#define NL 32     // MZI layers
#define NPE 512   // even pairs
#define NPO 511   // odd pairs
#define G3E 1536  // 3*NE

// Scratch (no allocations allowed -> __device__ globals)
__device__ float g_G[NV * G3E];       // token gate table: embed@W_ih^T + b_ih
__device__ float g_h[2][NB * NE];     // GRU hidden double buffer
__device__ float g_zc[NB * 2 * NM];   // h@Wc^T + bc
__device__ float g_pr[NB * NM];       // psi real
__device__ float g_pi[NB * NM];       // psi imag
__device__ float g_Wp[G3E * NE];      // gate-interleaved W_hh (tf32-rounded)
__device__ float g_bp[G3E];           // gate-interleaved b_hh

// ---------------------------------------------------------------------------
// tf32 helpers
// ---------------------------------------------------------------------------
__device__ __forceinline__ float to_tf32(float x) {
    unsigned u;
    asm("cvt.rna.tf32.f32 %0, %1;" : "=r"(u) : "f"(x));
    return __uint_as_float(u);
}

__device__ __forceinline__ void mma_tf32(float* c, const unsigned* a, const unsigned* b) {
    asm("mma.sync.aligned.m16n8k8.row.col.f32.tf32.tf32.f32 "
        "{%0,%1,%2,%3}, {%4,%5,%6,%7}, {%8,%9}, {%0,%1,%2,%3};"
        : "+f"(c[0]), "+f"(c[1]), "+f"(c[2]), "+f"(c[3])
        : "r"(a[0]), "r"(a[1]), "r"(a[2]), "r"(a[3]), "r"(b[0]), "r"(b[1]));
}

// ---------------------------------------------------------------------------
// Permute W_hh rows so gates interleave: Wp[e*3+g][k] = W_hh[g*512+e][k]
// (tf32-rounded). Also permute b_hh (kept fp32).
// ---------------------------------------------------------------------------
__global__ __launch_bounds__(256) void permute_whh(
    const float* __restrict__ W_hh, const float* __restrict__ b_hh)
{
    int idx = blockIdx.x * 256 + threadIdx.x;
    if (idx < G3E * NE) {
        int orow = idx >> 9;        // /512
        int k = idx & 511;
        int e = orow / 3, g = orow - 3 * e;
        g_Wp[idx] = to_tf32(W_hh[(size_t)(g * NE + e) * NE + k]);
    }
    if (idx < G3E) {
        int e = idx / 3, g = idx - 3 * e;
        g_bp[idx] = b_hh[g * NE + e];
    }
}

// ---------------------------------------------------------------------------
// Tensor-core GRU step: P = hin @ Wp^T (tf32 mma, fp32 acc), fused gate math.
// BM=128 rows, BN=96 cols (= 32 hidden units x 3 interleaved gates), BK=16.
// 256 threads = 8 warps (warp grid 4m x 2n, warp tile 32x48).
// Grid: (NE/32=16, NB/128=8) = 128 blocks.
// ---------------------------------------------------------------------------
#define BM 128
#define BNE 32
#define BN 96
#define BK 16
#define KTILES (NE / BK)   // 32

__global__ __launch_bounds__(256) void gru_step_mma(
    const float* __restrict__ hin, float* __restrict__ hout,
    const int* __restrict__ tokens, int t)
{
    // union: mainloop A/B tiles (17920B) vs C staging (25600B)
    __shared__ __align__(16) float smem[6400];
    float* As = smem;              // [128][20]
    float* Bs = smem + 128 * 20;   // [96][20]
    float* Cs = smem;              // [64][100] after mainloop

    int tid = threadIdx.x;
    int lane = tid & 31, w = tid >> 5;
    int g = lane >> 2, tq = lane & 3;
    int m0 = (w >> 1) * 32;        // warp row base in tile
    int n0 = (w & 1) * 48;         // warp col base in tile
    int rb = blockIdx.y * BM;      // global row base
    int ecb = blockIdx.x * BNE;    // global e base
    int cb = ecb * 3;              // global col base into permuted 1536

    // A loader: 512 float4 (128x16), 2 per thread
    int aRow0 = tid >> 2, aQ0 = tid & 3;
    int aRow1 = (tid + 256) >> 2, aQ1 = tid & 3;  // idx+256: q unchanged mod 4
    // B loader: 384 float4 (96x16), up to 2 per thread
    int bRow0 = tid >> 2, bQ0 = tid & 3;
    int bRow1 = (tid + 256) >> 2, bQ1 = tid & 3;
    bool bp1 = (tid < 128);

    float acc[2][6][4];
#pragma unroll
    for (int mi = 0; mi < 2; mi++)
#pragma unroll
        for (int ni = 0; ni < 6; ni++)
#pragma unroll
            for (int j = 0; j < 4; j++) acc[mi][ni][j] = 0.f;

    const float* Ag = hin + (size_t)rb * NE;
    const float* Bg = g_Wp + (size_t)cb * NE;

    // preload tile 0
    float4 pa0 = *(const float4*)(Ag + (size_t)aRow0 * NE + aQ0 * 4);
    float4 pa1 = *(const float4*)(Ag + (size_t)aRow1 * NE + aQ1 * 4);
    float4 pb0 = *(const float4*)(Bg + (size_t)bRow0 * NE + bQ0 * 4);
    float4 pb1 = bp1 ? *(const float4*)(Bg + (size_t)bRow1 * NE + bQ1 * 4)
                     : make_float4(0.f, 0.f, 0.f, 0.f);
    {
        float* d = As + aRow0 * 20 + aQ0 * 4;
        d[0] = to_tf32(pa0.x); d[1] = to_tf32(pa0.y); d[2] = to_tf32(pa0.z); d[3] = to_tf32(pa0.w);
        d = As + aRow1 * 20 + aQ1 * 4;
        d[0] = to_tf32(pa1.x); d[1] = to_tf32(pa1.y); d[2] = to_tf32(pa1.z); d[3] = to_tf32(pa1.w);
        d = Bs + bRow0 * 20 + bQ0 * 4;
        d[0] = pb0.x; d[1] = pb0.y; d[2] = pb0.z; d[3] = pb0.w;
        if (bp1) {
            d = Bs + bRow1 * 20 + bQ1 * 4;
            d[0] = pb1.x; d[1] = pb1.y; d[2] = pb1.z; d[3] = pb1.w;
        }
    }
    __syncthreads();

    for (int kt = 0; kt < KTILES; kt++) {
        float4 na0, na1, nb0, nb1;
        if (kt < KTILES - 1) {
            int k0 = (kt + 1) * BK;
            na0 = *(const float4*)(Ag + (size_t)aRow0 * NE + k0 + aQ0 * 4);
            na1 = *(const float4*)(Ag + (size_t)aRow1 * NE + k0 + aQ1 * 4);
            nb0 = *(const float4*)(Bg + (size_t)bRow0 * NE + k0 + bQ0 * 4);
            if (bp1) nb1 = *(const float4*)(Bg + (size_t)bRow1 * NE + k0 + bQ1 * 4);
        }

        // compute on current tile: 2 k-steps of k=8
#pragma unroll
        for (int ks = 0; ks < 2; ks++) {
            unsigned af[2][4];
#pragma unroll
            for (int mi = 0; mi < 2; mi++) {
                const float* ap = As + (m0 + 16 * mi) * 20 + ks * 8;
                af[mi][0] = __float_as_uint(ap[g * 20 + tq]);
                af[mi][1] = __float_as_uint(ap[(g + 8) * 20 + tq]);
                af[mi][2] = __float_as_uint(ap[g * 20 + tq + 4]);
                af[mi][3] = __float_as_uint(ap[(g + 8) * 20 + tq + 4]);
            }
#pragma unroll
            for (int ni = 0; ni < 6; ni++) {
                const float* bpp = Bs + (n0 + 8 * ni + g) * 20 + ks * 8;
                unsigned bf[2];
                bf[0] = __float_as_uint(bpp[tq]);
                bf[1] = __float_as_uint(bpp[tq + 4]);
                mma_tf32(acc[0][ni], af[0], bf);
                mma_tf32(acc[1][ni], af[1], bf);
            }
        }
        __syncthreads();
        if (kt < KTILES - 1) {
            float* d = As + aRow0 * 20 + aQ0 * 4;
            d[0] = to_tf32(na0.x); d[1] = to_tf32(na0.y); d[2] = to_tf32(na0.z); d[3] = to_tf32(na0.w);
            d = As + aRow1 * 20 + aQ1 * 4;
            d[0] = to_tf32(na1.x); d[1] = to_tf32(na1.y); d[2] = to_tf32(na1.z); d[3] = to_tf32(na1.w);
            d = Bs + bRow0 * 20 + bQ0 * 4;
            d[0] = nb0.x; d[1] = nb0.y; d[2] = nb0.z; d[3] = nb0.w;
            if (bp1) {
                d = Bs + bRow1 * 20 + bQ1 * 4;
                d[0] = nb1.x; d[1] = nb1.y; d[2] = nb1.z; d[3] = nb1.w;
            }
        }
        __syncthreads();
    }

    // Two-phase epilogue: stage 64 rows of C in smem, apply GRU gates.
#pragma unroll
    for (int phase = 0; phase < 2; phase++) {
        if (((w >> 1) >> 1) == phase) {
            int rloc = m0 - phase * 64;  // 0 or 32
#pragma unroll
            for (int mi = 0; mi < 2; mi++)
#pragma unroll
                for (int ni = 0; ni < 6; ni++) {
                    int col = n0 + 8 * ni + 2 * tq;
                    *(float2*)&Cs[(rloc + 16 * mi + g) * 100 + col] =
                        make_float2(acc[mi][ni][0], acc[mi][ni][1]);
                    *(float2*)&Cs[(rloc + 16 * mi + g + 8) * 100 + col] =
                        make_float2(acc[mi][ni][2], acc[mi][ni][3]);
                }
        }
        __syncthreads();

        for (int i = tid; i < 64 * 32; i += 256) {
            int e = i & 31, r = i >> 5;
            int rg = rb + phase * 64 + r;
            int eg = ecb + e;
            float hr = Cs[r * 100 + 3 * e]     + g_bp[3 * eg];
            float hz = Cs[r * 100 + 3 * e + 1] + g_bp[3 * eg + 1];
            float hn = Cs[r * 100 + 3 * e + 2] + g_bp[3 * eg + 2];
            int tok = tokens[rg * NT + t];
            const float* Gr = g_G + (size_t)tok * G3E;
            float ir = Gr[eg], iz = Gr[NE + eg], inn = Gr[2 * NE + eg];
            float rr = 1.f / (1.f + expf(-(ir + hr)));
            float zz = 1.f / (1.f + expf(-(iz + hz)));
            float nn = tanhf(inn + rr * hn);
            float hp = hin[(size_t)rg * NE + eg];
            hout[(size_t)rg * NE + eg] = (1.f - zz) * nn + zz * hp;
        }
        __syncthreads();
    }
}

// ---------------------------------------------------------------------------
// Generic tiled GEMM: C[Mr x Nc] = A[Mr x K] * Bm[Nc x K]^T + bias[Nc]
// (used for token gate table and zc projection)
// ---------------------------------------------------------------------------
__global__ __launch_bounds__(256) void gemm64_abT(
    const float* __restrict__ A, const float* __restrict__ Bm,
    const float* __restrict__ bias, float* __restrict__ C, int Nc, int K)
{
    __shared__ float As[64][17];
    __shared__ float Bs[16][65];
    int tid = threadIdx.x;
    int r4 = tid >> 2, q = tid & 3;
    int ty = tid >> 4, tx = tid & 15;
    int rb = blockIdx.y * 64, cb = blockIdx.x * 64;

    float acc[4][4];
#pragma unroll
    for (int i = 0; i < 4; i++)
#pragma unroll
        for (int j = 0; j < 4; j++) acc[i][j] = 0.f;

    for (int k0 = 0; k0 < K; k0 += 16) {
        float4 av = *(const float4*)(A + (size_t)(rb + r4) * K + k0 + q * 4);
        As[r4][q * 4 + 0] = av.x; As[r4][q * 4 + 1] = av.y;
        As[r4][q * 4 + 2] = av.z; As[r4][q * 4 + 3] = av.w;
        float4 bv = *(const float4*)(Bm + (size_t)(cb + r4) * K + k0 + q * 4);
        Bs[q * 4 + 0][r4] = bv.x; Bs[q * 4 + 1][r4] = bv.y;
        Bs[q * 4 + 2][r4] = bv.z; Bs[q * 4 + 3][r4] = bv.w;
        __syncthreads();
#pragma unroll
        for (int kk = 0; kk < 16; kk++) {
            float a[4], b[4];
#pragma unroll
            for (int i = 0; i < 4; i++) a[i] = As[ty * 4 + i][kk];
#pragma unroll
            for (int j = 0; j < 4; j++) b[j] = Bs[kk][tx * 4 + j];
#pragma unroll
            for (int i = 0; i < 4; i++)
#pragma unroll
                for (int j = 0; j < 4; j++) acc[i][j] = fmaf(a[i], b[j], acc[i][j]);
        }
        __syncthreads();
    }
#pragma unroll
    for (int i = 0; i < 4; i++) {
        int row = rb + ty * 4 + i;
#pragma unroll
        for (int j = 0; j < 4; j++) {
            int col = cb + tx * 4 + j;
            C[(size_t)row * Nc + col] = acc[i][j] + bias[col];
        }
    }
}

__global__ void zero_kernel(float* p, int n)
{
    int i = blockIdx.x * blockDim.x + threadIdx.x;
    if (i < n) p[i] = 0.f;
}

// ---------------------------------------------------------------------------
// psi init: split zc -> (re, im), complex_normalize per row.
// ---------------------------------------------------------------------------
__global__ __launch_bounds__(256) void psi_init_kernel()
{
    int b = blockIdx.x, tid = threadIdx.x;
    __shared__ float red[8];
    const float* zrow = g_zc + (size_t)b * 2 * NM;
    float ss = 0.f;
    for (int m = tid; m < NM; m += 256) {
        float re = zrow[m], im = zrow[NM + m];
        ss += re * re + im * im;
    }
    for (int o = 16; o; o >>= 1) ss += __shfl_xor_sync(0xffffffffu, ss, o);
    if ((tid & 31) == 0) red[tid >> 5] = ss;
    __syncthreads();
    if (tid < 8) {
        float v = red[tid];
        for (int o = 4; o; o >>= 1) v += __shfl_xor_sync(0xffu, v, o);
        if (tid == 0) red[0] = v;
    }
    __syncthreads();
    float inv = 1.f / sqrtf(red[0] + 1e-8f);
    for (int m = tid; m < NM; m += 256) {
        g_pr[(size_t)b * NM + m] = zrow[m] * inv;
        g_pi[(size_t)b * NM + m] = zrow[NM + m] * inv;
    }
}

// ---------------------------------------------------------------------------
// MZI layers: one block per batch row, psi row lives in SMEM for all 32 layers.
// ---------------------------------------------------------------------------
__device__ __forceinline__ void pair_apply(int a, int c, float tt, float pp, float rr,
                                           float* sre, float* sim)
{
    float st, ct; sincosf(tt, &st, &ct);
    float sp, cp; sincosf(pp, &sp, &cp);
    float sr, cr; sincosf(rr, &sr, &cr);
    float cpr = cp * cr - sp * sr;
    float spr = sp * cr + cp * sr;
    float u11r = ct * cpr, u11i = ct * spr;
    float u12r = -st * sp, u12i = st * cp;
    float u21r = -st * sr, u21i = st * cr;
    float u22  = ct;
    float v0r = sre[a], v0i = sim[a], v1r = sre[c], v1i = sim[c];
    float n0r = u11r * v0r - u11i * v0i + u12r * v1r - u12i * v1i;
    float n0i = u11r * v0i + u11i * v0r + u12r * v1i + u12i * v1r;
    float n1r = u21r * v0r - u21i * v0i + u22 * v1r;
    float n1i = u21r * v0i + u21i * v0r + u22 * v1i;
    sre[a] = n0r; sim[a] = n0i; sre[c] = n1r; sim[c] = n1i;
}

__global__ __launch_bounds__(512) void mzi_kernel(
    const float* __restrict__ phase, const float* __restrict__ te,
    const float* __restrict__ pe, const float* __restrict__ re_,
    const float* __restrict__ to, const float* __restrict__ po,
    const float* __restrict__ ro)
{
    __shared__ float sre[NM], sim[NM];
    __shared__ float red[16];
    int b = blockIdx.x, tid = threadIdx.x;
    sre[tid] = g_pr[(size_t)b * NM + tid];
    sre[tid + 512] = g_pr[(size_t)b * NM + tid + 512];
    sim[tid] = g_pi[(size_t)b * NM + tid];
    sim[tid + 512] = g_pi[(size_t)b * NM + tid + 512];
    __syncthreads();

    for (int l = 0; l < NL; l++) {
#pragma unroll
        for (int h = 0; h < 2; h++) {
            int mm = tid + h * 512;
            float s, c; sincosf(phase[l * NM + mm], &s, &c);
            float r0 = sre[mm], i0 = sim[mm];
            sre[mm] = r0 * c - i0 * s;
            sim[mm] = r0 * s + i0 * c;
        }
        __syncthreads();
        pair_apply(2 * tid, 2 * tid + 1,
                   te[l * NPE + tid], pe[l * NPE + tid], re_[l * NPE + tid], sre, sim);
        __syncthreads();
        if (tid < NPO)
            pair_apply(2 * tid + 1, 2 * tid + 2,
                       to[l * NPO + tid], po[l * NPO + tid], ro[l * NPO + tid], sre, sim);
        __syncthreads();
        float ss = sre[tid] * sre[tid] + sim[tid] * sim[tid]
                 + sre[tid + 512] * sre[tid + 512] + sim[tid + 512] * sim[tid + 512];
        for (int o = 16; o; o >>= 1) ss += __shfl_xor_sync(0xffffffffu, ss, o);
        if ((tid & 31) == 0) red[tid >> 5] = ss;
        __syncthreads();
        if (tid < 16) {
            float v = red[tid];
            for (int o = 8; o; o >>= 1) v += __shfl_xor_sync(0xffffu, v, o);
            if (tid == 0) red[0] = v;
        }
        __syncthreads();
        float inv = 1.f / sqrtf(red[0] + 1e-8f);
        sre[tid] *= inv; sim[tid] *= inv;
        sre[tid + 512] *= inv; sim[tid + 512] *= inv;
        __syncthreads();
    }

    g_pr[(size_t)b * NM + tid] = sre[tid];
    g_pr[(size_t)b * NM + tid + 512] = sre[tid + 512];
    g_pi[(size_t)b * NM + tid] = sim[tid];
    g_pi[(size_t)b * NM + tid + 512] = sim[tid + 512];
}

// ---------------------------------------------------------------------------
// Readout: amps = psi @ R^T (complex), out = log(|amps|^2 + 1e-12).
// ---------------------------------------------------------------------------
__global__ __launch_bounds__(256) void readout_kernel(
    const float* __restrict__ Rr, const float* __restrict__ Ri,
    float* __restrict__ out)
{
    __shared__ float Ar[64][17], Ai[64][17];
    __shared__ float Br[16][65], Bi[16][65];
    int tid = threadIdx.x;
    int r4 = tid >> 2, q = tid & 3;
    int ty = tid >> 4, tx = tid & 15;
    int rb = blockIdx.y * 64, cb = blockIdx.x * 64;

    float accr[4][4], acci[4][4];
#pragma unroll
    for (int i = 0; i < 4; i++)
#pragma unroll
        for (int j = 0; j < 4; j++) { accr[i][j] = 0.f; acci[i][j] = 0.f; }

    for (int k0 = 0; k0 < NM; k0 += 16) {
        float4 v;
        v = *(const float4*)(g_pr + (size_t)(rb + r4) * NM + k0 + q * 4);
        Ar[r4][q * 4 + 0] = v.x; Ar[r4][q * 4 + 1] = v.y;
        Ar[r4][q * 4 + 2] = v.z; Ar[r4][q * 4 + 3] = v.w;
        v = *(const float4*)(g_pi + (size_t)(rb + r4) * NM + k0 + q * 4);
        Ai[r4][q * 4 + 0] = v.x; Ai[r4][q * 4 + 1] = v.y;
        Ai[r4][q * 4 + 2] = v.z; Ai[r4][q * 4 + 3] = v.w;
        v = *(const float4*)(Rr + (size_t)(cb + r4) * NM + k0 + q * 4);
        Br[q * 4 + 0][r4] = v.x; Br[q * 4 + 1][r4] = v.y;
        Br[q * 4 + 2][r4] = v.z; Br[q * 4 + 3][r4] = v.w;
        v = *(const float4*)(Ri + (size_t)(cb + r4) * NM + k0 + q * 4);
        Bi[q * 4 + 0][r4] = v.x; Bi[q * 4 + 1][r4] = v.y;
        Bi[q * 4 + 2][r4] = v.z; Bi[q * 4 + 3][r4] = v.w;
        __syncthreads();
#pragma unroll
        for (int kk = 0; kk < 16; kk++) {
            float par[4], pai[4], wbr[4], wbi[4];
#pragma unroll
            for (int i = 0; i < 4; i++) { par[i] = Ar[ty * 4 + i][kk]; pai[i] = Ai[ty * 4 + i][kk]; }
#pragma unroll
            for (int j = 0; j < 4; j++) { wbr[j] = Br[kk][tx * 4 + j]; wbi[j] = Bi[kk][tx * 4 + j]; }
#pragma unroll
            for (int i = 0; i < 4; i++)
#pragma unroll
                for (int j = 0; j < 4; j++) {
                    accr[i][j] = fmaf(par[i], wbr[j], accr[i][j]);
                    accr[i][j] = fmaf(-pai[i], wbi[j], accr[i][j]);
                    acci[i][j] = fmaf(par[i], wbi[j], acci[i][j]);
                    acci[i][j] = fmaf(pai[i], wbr[j], acci[i][j]);
                }
        }
        __syncthreads();
    }
#pragma unroll
    for (int i = 0; i < 4; i++) {
        int row = rb + ty * 4 + i;
#pragma unroll
        for (int j = 0; j < 4; j++) {
            int col = cb + tx * 4 + j;
            float ar = accr[i][j], ai = acci[i][j];
            out[(size_t)row * NV + col] = logf(ar * ar + ai * ai + 1e-12f);
        }
    }
}

// ---------------------------------------------------------------------------
// Row-wise logsumexp, subtract in place.
// ---------------------------------------------------------------------------
__global__ __launch_bounds__(256) void lse_kernel(float* __restrict__ out)
{
    int b = blockIdx.x, tid = threadIdx.x;
    __shared__ float red[8];
    float* row = out + (size_t)b * NV;

    float mx = -INFINITY;
    for (int v = tid; v < NV; v += 256) mx = fmaxf(mx, row[v]);
    for (int o = 16; o; o >>= 1) mx = fmaxf(mx, __shfl_xor_sync(0xffffffffu, mx, o));
    if ((tid & 31) == 0) red[tid >> 5] = mx;
    __syncthreads();
    if (tid < 8) {
        float v = red[tid];
        for (int o = 4; o; o >>= 1) v = fmaxf(v, __shfl_xor_sync(0xffu, v, o));
        if (tid == 0) red[0] = v;
    }
    __syncthreads();
    mx = red[0];
    __syncthreads();

    float se = 0.f;
    for (int v = tid; v < NV; v += 256) se += expf(row[v] - mx);
    for (int o = 16; o; o >>= 1) se += __shfl_xor_sync(0xffffffffu, se, o);
    if ((tid & 31) == 0) red[tid >> 5] = se;
    __syncthreads();
    if (tid < 8) {
        float v = red[tid];
        for (int o = 4; o; o >>= 1) v += __shfl_xor_sync(0xffu, v, o);
        if (tid == 0) red[0] = v;
    }
    __syncthreads();
    float lse = mx + logf(red[0]);
    for (int v = tid; v < NV; v += 256) row[v] -= lse;
}

// ---------------------------------------------------------------------------
extern "C" void kernel_launch(void* const* d_in, const int* in_sizes, int n_in,
                              void* d_out, int out_size)
{
    const int*   tokens = (const int*)d_in[0];
    const float* embed  = (const float*)d_in[1];
    const float* W_ih   = (const float*)d_in[2];
    const float* W_hh   = (const float*)d_in[3];
    const float* b_ih   = (const float*)d_in[4];
    const float* b_hh   = (const float*)d_in[5];
    const float* Wc     = (const float*)d_in[6];
    const float* bc     = (const float*)d_in[7];
    const float* phase  = (const float*)d_in[8];
    const float* te     = (const float*)d_in[9];
    const float* pe     = (const float*)d_in[10];
    const float* re_    = (const float*)d_in[11];
    const float* to     = (const float*)d_in[12];
    const float* po     = (const float*)d_in[13];
    const float* ro     = (const float*)d_in[14];
    const float* Rr     = (const float*)d_in[15];
    const float* Ri     = (const float*)d_in[16];
    float* out = (float*)d_out;

    static float* pG = nullptr;
    static float* pH = nullptr;
    static float* pZC = nullptr;
    if (!pG) {
        cudaGetSymbolAddress((void**)&pG, g_G);
        cudaGetSymbolAddress((void**)&pH, g_h);
        cudaGetSymbolAddress((void**)&pZC, g_zc);
    }
    float* pH0 = pH;
    float* pH1 = pH + NB * NE;

    // 0. Gate-interleave + tf32-round W_hh, permute b_hh
    permute_whh<<<(G3E * NE + 255) / 256, 256>>>(W_hh, b_hh);

    // 1. Token gate table: G = embed @ W_ih^T + b_ih  (V x 3E)
    gemm64_abT<<<dim3(G3E / 64, NV / 64), 256>>>(embed, W_ih, b_ih, pG, G3E, NE);

    // 2. h0 = 0
    zero_kernel<<<(NB * NE + 255) / 256, 256>>>(pH0, NB * NE);

    // 3. GRU recurrence on tensor cores, double-buffered
    for (int t = 0; t < NT; t++) {
        const float* hin = (t & 1) ? pH1 : pH0;
        float* hout      = (t & 1) ? pH0 : pH1;
        gru_step_mma<<<dim3(NE / BNE, NB / BM), 256>>>(hin, hout, tokens, t);
    }

    // 4. zc = h @ Wc^T + bc, then normalized complex psi
    gemm64_abT<<<dim3(2 * NM / 64, NB / 64), 256>>>(pH0, Wc, bc, pZC, 2 * NM, NE);
    psi_init_kernel<<<NB, 256>>>();

    // 5. 32 MZI layers, persistent row in SMEM
    mzi_kernel<<<NB, 512>>>(phase, te, pe, re_, to, po, ro);

    // 6. Readout complex GEMM + log|.|^2, then row logsumexp
    readout_kernel<<<dim3(NV / 64, NB / 64), 256>>>(Rr, Ri, out);
    lse_kernel<<<NB, 256>>>(out);
}

// round 4
// speedup vs baseline: 2.0437x; 1.1797x over previous
#include <cuda_runtime.h>
#include <math.h>

// Problem dims
#define NB 1024   // batch
#define NT 64     // time steps
#define NV 1024   // vocab
#define NE 512    // embed dim
#define NM 1024   // modes
#define NL 32     // MZI layers
#define NPE 512   // even pairs
#define NPO 511   // odd pairs
#define G3E 1536  // 3*NE

// Scratch (no allocations allowed -> __device__ globals)
__device__ float g_G[NV * G3E];       // token gate table: embed@W_ih^T + b_ih
__device__ float g_h[2][NB * NE];     // GRU hidden double buffer
__device__ float g_zc[NB * 2 * NM];   // h@Wc^T + bc
__device__ float g_pr[NB * NM];       // psi real
__device__ float g_pi[NB * NM];       // psi imag
__device__ float g_Wp[G3E * NE];      // gate-interleaved W_hh (tf32-rounded)
__device__ float g_bp[G3E];           // gate-interleaved b_hh
__device__ unsigned g_barCount;       // grid barrier state
__device__ unsigned g_barGen;

// ---------------------------------------------------------------------------
// tf32 helpers
// ---------------------------------------------------------------------------
__device__ __forceinline__ float to_tf32(float x) {
    unsigned u;
    asm("cvt.rna.tf32.f32 %0, %1;" : "=r"(u) : "f"(x));
    return __uint_as_float(u);
}

__device__ __forceinline__ void mma_tf32(float* c, const unsigned* a, const unsigned* b) {
    asm("mma.sync.aligned.m16n8k8.row.col.f32.tf32.tf32.f32 "
        "{%0,%1,%2,%3}, {%4,%5,%6,%7}, {%8,%9}, {%0,%1,%2,%3};"
        : "+f"(c[0]), "+f"(c[1]), "+f"(c[2]), "+f"(c[3])
        : "r"(a[0]), "r"(a[1]), "r"(a[2]), "r"(a[3]), "r"(b[0]), "r"(b[1]));
}

// ---------------------------------------------------------------------------
// Grid-wide spin barrier. Safe because all 128 CTAs are wave-1 resident
// (218KB smem -> 1 CTA/SM, 128 <= 148 SMs). State reset by init kernel.
// ---------------------------------------------------------------------------
#define NCTA 128
__device__ __forceinline__ void grid_sync()
{
    __threadfence();
    __syncthreads();
    if (threadIdx.x == 0) {
        unsigned gen = *(volatile unsigned*)&g_barGen;
        if (atomicAdd(&g_barCount, 1u) == NCTA - 1) {
            g_barCount = 0;
            __threadfence();
            atomicExch(&g_barGen, gen + 1u);
        } else {
            while (*(volatile unsigned*)&g_barGen == gen) { }
            __threadfence();
        }
    }
    __syncthreads();
}

// ---------------------------------------------------------------------------
// Permute W_hh rows so gates interleave: Wp[e*3+g][k] = W_hh[g*512+e][k]
// (tf32-rounded). Also permute b_hh (kept fp32).
// ---------------------------------------------------------------------------
__global__ __launch_bounds__(256) void permute_whh(
    const float* __restrict__ W_hh, const float* __restrict__ b_hh)
{
    int idx = blockIdx.x * 256 + threadIdx.x;
    if (idx < G3E * NE) {
        int orow = idx >> 9;        // /512
        int k = idx & 511;
        int e = orow / 3, g = orow - 3 * e;
        g_Wp[idx] = to_tf32(W_hh[(size_t)(g * NE + e) * NE + k]);
    }
    if (idx < G3E) {
        int e = idx / 3, g = idx - 3 * e;
        g_bp[idx] = b_hh[g * NE + e];
    }
}

// ---------------------------------------------------------------------------
// Persistent GRU: one kernel runs all 64 timesteps. Each CTA owns a
// 128-row x 32-e tile (96 gate cols); its W slice (96x512 tf32) lives in
// SMEM for the whole kernel. Grid barrier between steps.
// Warp grid 4m x 2n, warp tile 32x48 (m16n8k8 tf32 MMA).
// ---------------------------------------------------------------------------
#define WS_STRIDE 516                   // 516 % 32 == 4 -> conflict-free frags
#define AS_STAGE  (128 * 20)            // one A stage: 128 rows x 16k (pad 20)
#define SMEM_FLOATS (96 * WS_STRIDE + 2 * AS_STAGE)
#define SMEM_BYTES (SMEM_FLOATS * 4)    // 218,624 B

__global__ __launch_bounds__(256, 1) void gru_persist(
    float* __restrict__ h0, float* __restrict__ h1,
    const int* __restrict__ tokens)
{
    extern __shared__ float smem[];
    float* Ws = smem;                    // [96][516]
    float* As = smem + 96 * WS_STRIDE;   // [2][128][20]
    float* Cs = As;                      // epilogue staging reuses A space

    int tid = threadIdx.x;
    int lane = tid & 31, w = tid >> 5;
    int g = lane >> 2, tq = lane & 3;
    int m0 = (w >> 1) * 32;              // warp row base in tile
    int n0 = (w & 1) * 48;               // warp col base in tile
    int rb = blockIdx.y * 128;           // global row base
    int ecb = blockIdx.x * 32;           // global e base
    int cb = ecb * 3;                    // global gate-col base

    // ---- one-time: load W slice (96 x 512) into SMEM ----
    for (int i = tid; i < 96 * 128; i += 256) {
        int row = i >> 7, q4 = i & 127;
        float4 v = *(const float4*)(g_Wp + (size_t)(cb + row) * NE + q4 * 4);
        float* d = Ws + row * WS_STRIDE + q4 * 4;
        d[0] = v.x; d[1] = v.y; d[2] = v.z; d[3] = v.w;
    }
    __syncthreads();

    // A loader mapping: 512 float4 per 128x16 tile, 2 per thread
    int aRow0 = tid >> 2, aRow1 = 64 + (tid >> 2), aQ = tid & 3;

    for (int t = 0; t < NT; t++) {
        const float* hin = (t & 1) ? h1 : h0;
        float* hout      = (t & 1) ? h0 : h1;
        const float* Ag = hin + (size_t)rb * NE;

        // preload k-tile 0 into stage 0
        {
            float4 a0 = *(const float4*)(Ag + (size_t)aRow0 * NE + aQ * 4);
            float4 a1 = *(const float4*)(Ag + (size_t)aRow1 * NE + aQ * 4);
            float* d = As + aRow0 * 20 + aQ * 4;
            d[0] = to_tf32(a0.x); d[1] = to_tf32(a0.y); d[2] = to_tf32(a0.z); d[3] = to_tf32(a0.w);
            d = As + aRow1 * 20 + aQ * 4;
            d[0] = to_tf32(a1.x); d[1] = to_tf32(a1.y); d[2] = to_tf32(a1.z); d[3] = to_tf32(a1.w);
        }
        __syncthreads();

        float acc[2][6][4];
#pragma unroll
        for (int mi = 0; mi < 2; mi++)
#pragma unroll
            for (int ni = 0; ni < 6; ni++)
#pragma unroll
                for (int j = 0; j < 4; j++) acc[mi][ni][j] = 0.f;

        for (int kt = 0; kt < 32; kt++) {
            const float* Acur = As + (kt & 1) * AS_STAGE;
            float4 na0, na1;
            if (kt < 31) {
                int k0 = (kt + 1) * 16;
                na0 = *(const float4*)(Ag + (size_t)aRow0 * NE + k0 + aQ * 4);
                na1 = *(const float4*)(Ag + (size_t)aRow1 * NE + k0 + aQ * 4);
            }
#pragma unroll
            for (int ks = 0; ks < 2; ks++) {
                unsigned af[2][4];
#pragma unroll
                for (int mi = 0; mi < 2; mi++) {
                    const float* ap = Acur + (m0 + 16 * mi) * 20 + ks * 8;
                    af[mi][0] = __float_as_uint(ap[g * 20 + tq]);
                    af[mi][1] = __float_as_uint(ap[(g + 8) * 20 + tq]);
                    af[mi][2] = __float_as_uint(ap[g * 20 + tq + 4]);
                    af[mi][3] = __float_as_uint(ap[(g + 8) * 20 + tq + 4]);
                }
#pragma unroll
                for (int ni = 0; ni < 6; ni++) {
                    const float* bpp = Ws + (n0 + 8 * ni + g) * WS_STRIDE + kt * 16 + ks * 8;
                    unsigned bf[2];
                    bf[0] = __float_as_uint(bpp[tq]);
                    bf[1] = __float_as_uint(bpp[tq + 4]);
                    mma_tf32(acc[0][ni], af[0], bf);
                    mma_tf32(acc[1][ni], af[1], bf);
                }
            }
            if (kt < 31) {
                float* d = As + ((kt + 1) & 1) * AS_STAGE + aRow0 * 20 + aQ * 4;
                d[0] = to_tf32(na0.x); d[1] = to_tf32(na0.y); d[2] = to_tf32(na0.z); d[3] = to_tf32(na0.w);
                d = As + ((kt + 1) & 1) * AS_STAGE + aRow1 * 20 + aQ * 4;
                d[0] = to_tf32(na1.x); d[1] = to_tf32(na1.y); d[2] = to_tf32(na1.z); d[3] = to_tf32(na1.w);
            }
            __syncthreads();
        }

        // ---- epilogue: 4 phases of 32 rows, stage C in smem, gate math ----
#pragma unroll
        for (int p = 0; p < 4; p++) {
            if ((w >> 1) == p) {
#pragma unroll
                for (int mi = 0; mi < 2; mi++)
#pragma unroll
                    for (int ni = 0; ni < 6; ni++) {
                        int col = n0 + 8 * ni + 2 * tq;
                        *(float2*)&Cs[(16 * mi + g) * 100 + col] =
                            make_float2(acc[mi][ni][0], acc[mi][ni][1]);
                        *(float2*)&Cs[(16 * mi + g + 8) * 100 + col] =
                            make_float2(acc[mi][ni][2], acc[mi][ni][3]);
                    }
            }
            __syncthreads();

#pragma unroll
            for (int i = tid; i < 32 * 32; i += 256) {
                int e = i & 31, r = i >> 5;
                int rg = rb + p * 32 + r;
                int eg = ecb + e;
                float hr = Cs[r * 100 + 3 * e]     + g_bp[3 * eg];
                float hz = Cs[r * 100 + 3 * e + 1] + g_bp[3 * eg + 1];
                float hn = Cs[r * 100 + 3 * e + 2] + g_bp[3 * eg + 2];
                int tok = tokens[rg * NT + t];
                const float* Gr = g_G + (size_t)tok * G3E;
                float ir = Gr[eg], iz = Gr[NE + eg], inn = Gr[2 * NE + eg];
                float rr = 1.f / (1.f + expf(-(ir + hr)));
                float zz = 1.f / (1.f + expf(-(iz + hz)));
                float nn = tanhf(inn + rr * hn);
                float hp = hin[(size_t)rg * NE + eg];
                hout[(size_t)rg * NE + eg] = (1.f - zz) * nn + zz * hp;
            }
            __syncthreads();
        }

        // all CTAs' hout writes must land before next step reads them
        grid_sync();
    }
}

// ---------------------------------------------------------------------------
// Generic tiled GEMM: C[Mr x Nc] = A[Mr x K] * Bm[Nc x K]^T + bias[Nc]
// ---------------------------------------------------------------------------
__global__ __launch_bounds__(256) void gemm64_abT(
    const float* __restrict__ A, const float* __restrict__ Bm,
    const float* __restrict__ bias, float* __restrict__ C, int Nc, int K)
{
    __shared__ float As[64][17];
    __shared__ float Bs[16][65];
    int tid = threadIdx.x;
    int r4 = tid >> 2, q = tid & 3;
    int ty = tid >> 4, tx = tid & 15;
    int rb = blockIdx.y * 64, cb = blockIdx.x * 64;

    float acc[4][4];
#pragma unroll
    for (int i = 0; i < 4; i++)
#pragma unroll
        for (int j = 0; j < 4; j++) acc[i][j] = 0.f;

    for (int k0 = 0; k0 < K; k0 += 16) {
        float4 av = *(const float4*)(A + (size_t)(rb + r4) * K + k0 + q * 4);
        As[r4][q * 4 + 0] = av.x; As[r4][q * 4 + 1] = av.y;
        As[r4][q * 4 + 2] = av.z; As[r4][q * 4 + 3] = av.w;
        float4 bv = *(const float4*)(Bm + (size_t)(cb + r4) * K + k0 + q * 4);
        Bs[q * 4 + 0][r4] = bv.x; Bs[q * 4 + 1][r4] = bv.y;
        Bs[q * 4 + 2][r4] = bv.z; Bs[q * 4 + 3][r4] = bv.w;
        __syncthreads();
#pragma unroll
        for (int kk = 0; kk < 16; kk++) {
            float a[4], b[4];
#pragma unroll
            for (int i = 0; i < 4; i++) a[i] = As[ty * 4 + i][kk];
#pragma unroll
            for (int j = 0; j < 4; j++) b[j] = Bs[kk][tx * 4 + j];
#pragma unroll
            for (int i = 0; i < 4; i++)
#pragma unroll
                for (int j = 0; j < 4; j++) acc[i][j] = fmaf(a[i], b[j], acc[i][j]);
        }
        __syncthreads();
    }
#pragma unroll
    for (int i = 0; i < 4; i++) {
        int row = rb + ty * 4 + i;
#pragma unroll
        for (int j = 0; j < 4; j++) {
            int col = cb + tx * 4 + j;
            C[(size_t)row * Nc + col] = acc[i][j] + bias[col];
        }
    }
}

__global__ void init_kernel(float* h0)
{
    int i = blockIdx.x * blockDim.x + threadIdx.x;
    if (i < NB * NE) h0[i] = 0.f;
    if (i == 0) { g_barCount = 0u; g_barGen = 0u; }
}

// ---------------------------------------------------------------------------
// psi init: split zc -> (re, im), complex_normalize per row.
// ---------------------------------------------------------------------------
__global__ __launch_bounds__(256) void psi_init_kernel()
{
    int b = blockIdx.x, tid = threadIdx.x;
    __shared__ float red[8];
    const float* zrow = g_zc + (size_t)b * 2 * NM;
    float ss = 0.f;
    for (int m = tid; m < NM; m += 256) {
        float re = zrow[m], im = zrow[NM + m];
        ss += re * re + im * im;
    }
    for (int o = 16; o; o >>= 1) ss += __shfl_xor_sync(0xffffffffu, ss, o);
    if ((tid & 31) == 0) red[tid >> 5] = ss;
    __syncthreads();
    if (tid < 8) {
        float v = red[tid];
        for (int o = 4; o; o >>= 1) v += __shfl_xor_sync(0xffu, v, o);
        if (tid == 0) red[0] = v;
    }
    __syncthreads();
    float inv = 1.f / sqrtf(red[0] + 1e-8f);
    for (int m = tid; m < NM; m += 256) {
        g_pr[(size_t)b * NM + m] = zrow[m] * inv;
        g_pi[(size_t)b * NM + m] = zrow[NM + m] * inv;
    }
}

// ---------------------------------------------------------------------------
// MZI layers: one block per batch row, psi row lives in SMEM for all 32 layers.
// ---------------------------------------------------------------------------
__device__ __forceinline__ void pair_apply(int a, int c, float tt, float pp, float rr,
                                           float* sre, float* sim)
{
    float st, ct; sincosf(tt, &st, &ct);
    float sp, cp; sincosf(pp, &sp, &cp);
    float sr, cr; sincosf(rr, &sr, &cr);
    float cpr = cp * cr - sp * sr;
    float spr = sp * cr + cp * sr;
    float u11r = ct * cpr, u11i = ct * spr;
    float u12r = -st * sp, u12i = st * cp;
    float u21r = -st * sr, u21i = st * cr;
    float u22  = ct;
    float v0r = sre[a], v0i = sim[a], v1r = sre[c], v1i = sim[c];
    float n0r = u11r * v0r - u11i * v0i + u12r * v1r - u12i * v1i;
    float n0i = u11r * v0i + u11i * v0r + u12r * v1i + u12i * v1r;
    float n1r = u21r * v0r - u21i * v0i + u22 * v1r;
    float n1i = u21r * v0i + u21i * v0r + u22 * v1i;
    sre[a] = n0r; sim[a] = n0i; sre[c] = n1r; sim[c] = n1i;
}

__global__ __launch_bounds__(512) void mzi_kernel(
    const float* __restrict__ phase, const float* __restrict__ te,
    const float* __restrict__ pe, const float* __restrict__ re_,
    const float* __restrict__ to, const float* __restrict__ po,
    const float* __restrict__ ro)
{
    __shared__ float sre[NM], sim[NM];
    __shared__ float red[16];
    int b = blockIdx.x, tid = threadIdx.x;
    sre[tid] = g_pr[(size_t)b * NM + tid];
    sre[tid + 512] = g_pr[(size_t)b * NM + tid + 512];
    sim[tid] = g_pi[(size_t)b * NM + tid];
    sim[tid + 512] = g_pi[(size_t)b * NM + tid + 512];
    __syncthreads();

    for (int l = 0; l < NL; l++) {
#pragma unroll
        for (int h = 0; h < 2; h++) {
            int mm = tid + h * 512;
            float s, c; sincosf(phase[l * NM + mm], &s, &c);
            float r0 = sre[mm], i0 = sim[mm];
            sre[mm] = r0 * c - i0 * s;
            sim[mm] = r0 * s + i0 * c;
        }
        __syncthreads();
        pair_apply(2 * tid, 2 * tid + 1,
                   te[l * NPE + tid], pe[l * NPE + tid], re_[l * NPE + tid], sre, sim);
        __syncthreads();
        if (tid < NPO)
            pair_apply(2 * tid + 1, 2 * tid + 2,
                       to[l * NPO + tid], po[l * NPO + tid], ro[l * NPO + tid], sre, sim);
        __syncthreads();
        float ss = sre[tid] * sre[tid] + sim[tid] * sim[tid]
                 + sre[tid + 512] * sre[tid + 512] + sim[tid + 512] * sim[tid + 512];
        for (int o = 16; o; o >>= 1) ss += __shfl_xor_sync(0xffffffffu, ss, o);
        if ((tid & 31) == 0) red[tid >> 5] = ss;
        __syncthreads();
        if (tid < 16) {
            float v = red[tid];
            for (int o = 8; o; o >>= 1) v += __shfl_xor_sync(0xffffu, v, o);
            if (tid == 0) red[0] = v;
        }
        __syncthreads();
        float inv = 1.f / sqrtf(red[0] + 1e-8f);
        sre[tid] *= inv; sim[tid] *= inv;
        sre[tid + 512] *= inv; sim[tid + 512] *= inv;
        __syncthreads();
    }

    g_pr[(size_t)b * NM + tid] = sre[tid];
    g_pr[(size_t)b * NM + tid + 512] = sre[tid + 512];
    g_pi[(size_t)b * NM + tid] = sim[tid];
    g_pi[(size_t)b * NM + tid + 512] = sim[tid + 512];
}

// ---------------------------------------------------------------------------
// Readout: amps = psi @ R^T (complex), out = log(|amps|^2 + 1e-12).
// ---------------------------------------------------------------------------
__global__ __launch_bounds__(256) void readout_kernel(
    const float* __restrict__ Rr, const float* __restrict__ Ri,
    float* __restrict__ out)
{
    __shared__ float Ar[64][17], Ai[64][17];
    __shared__ float Br[16][65], Bi[16][65];
    int tid = threadIdx.x;
    int r4 = tid >> 2, q = tid & 3;
    int ty = tid >> 4, tx = tid & 15;
    int rb = blockIdx.y * 64, cb = blockIdx.x * 64;

    float accr[4][4], acci[4][4];
#pragma unroll
    for (int i = 0; i < 4; i++)
#pragma unroll
        for (int j = 0; j < 4; j++) { accr[i][j] = 0.f; acci[i][j] = 0.f; }

    for (int k0 = 0; k0 < NM; k0 += 16) {
        float4 v;
        v = *(const float4*)(g_pr + (size_t)(rb + r4) * NM + k0 + q * 4);
        Ar[r4][q * 4 + 0] = v.x; Ar[r4][q * 4 + 1] = v.y;
        Ar[r4][q * 4 + 2] = v.z; Ar[r4][q * 4 + 3] = v.w;
        v = *(const float4*)(g_pi + (size_t)(rb + r4) * NM + k0 + q * 4);
        Ai[r4][q * 4 + 0] = v.x; Ai[r4][q * 4 + 1] = v.y;
        Ai[r4][q * 4 + 2] = v.z; Ai[r4][q * 4 + 3] = v.w;
        v = *(const float4*)(Rr + (size_t)(cb + r4) * NM + k0 + q * 4);
        Br[q * 4 + 0][r4] = v.x; Br[q * 4 + 1][r4] = v.y;
        Br[q * 4 + 2][r4] = v.z; Br[q * 4 + 3][r4] = v.w;
        v = *(const float4*)(Ri + (size_t)(cb + r4) * NM + k0 + q * 4);
        Bi[q * 4 + 0][r4] = v.x; Bi[q * 4 + 1][r4] = v.y;
        Bi[q * 4 + 2][r4] = v.z; Bi[q * 4 + 3][r4] = v.w;
        __syncthreads();
#pragma unroll
        for (int kk = 0; kk < 16; kk++) {
            float par[4], pai[4], wbr[4], wbi[4];
#pragma unroll
            for (int i = 0; i < 4; i++) { par[i] = Ar[ty * 4 + i][kk]; pai[i] = Ai[ty * 4 + i][kk]; }
#pragma unroll
            for (int j = 0; j < 4; j++) { wbr[j] = Br[kk][tx * 4 + j]; wbi[j] = Bi[kk][tx * 4 + j]; }
#pragma unroll
            for (int i = 0; i < 4; i++)
#pragma unroll
                for (int j = 0; j < 4; j++) {
                    accr[i][j] = fmaf(par[i], wbr[j], accr[i][j]);
                    accr[i][j] = fmaf(-pai[i], wbi[j], accr[i][j]);
                    acci[i][j] = fmaf(par[i], wbi[j], acci[i][j]);
                    acci[i][j] = fmaf(pai[i], wbr[j], acci[i][j]);
                }
        }
        __syncthreads();
    }
#pragma unroll
    for (int i = 0; i < 4; i++) {
        int row = rb + ty * 4 + i;
#pragma unroll
        for (int j = 0; j < 4; j++) {
            int col = cb + tx * 4 + j;
            float ar = accr[i][j], ai = acci[i][j];
            out[(size_t)row * NV + col] = logf(ar * ar + ai * ai + 1e-12f);
        }
    }
}

// ---------------------------------------------------------------------------
// Row-wise logsumexp, subtract in place.
// ---------------------------------------------------------------------------
__global__ __launch_bounds__(256) void lse_kernel(float* __restrict__ out)
{
    int b = blockIdx.x, tid = threadIdx.x;
    __shared__ float red[8];
    float* row = out + (size_t)b * NV;

    float mx = -INFINITY;
    for (int v = tid; v < NV; v += 256) mx = fmaxf(mx, row[v]);
    for (int o = 16; o; o >>= 1) mx = fmaxf(mx, __shfl_xor_sync(0xffffffffu, mx, o));
    if ((tid & 31) == 0) red[tid >> 5] = mx;
    __syncthreads();
    if (tid < 8) {
        float v = red[tid];
        for (int o = 4; o; o >>= 1) v = fmaxf(v, __shfl_xor_sync(0xffu, v, o));
        if (tid == 0) red[0] = v;
    }
    __syncthreads();
    mx = red[0];
    __syncthreads();

    float se = 0.f;
    for (int v = tid; v < NV; v += 256) se += expf(row[v] - mx);
    for (int o = 16; o; o >>= 1) se += __shfl_xor_sync(0xffffffffu, se, o);
    if ((tid & 31) == 0) red[tid >> 5] = se;
    __syncthreads();
    if (tid < 8) {
        float v = red[tid];
        for (int o = 4; o; o >>= 1) v += __shfl_xor_sync(0xffu, v, o);
        if (tid == 0) red[0] = v;
    }
    __syncthreads();
    float lse = mx + logf(red[0]);
    for (int v = tid; v < NV; v += 256) row[v] -= lse;
}

// ---------------------------------------------------------------------------
extern "C" void kernel_launch(void* const* d_in, const int* in_sizes, int n_in,
                              void* d_out, int out_size)
{
    const int*   tokens = (const int*)d_in[0];
    const float* embed  = (const float*)d_in[1];
    const float* W_ih   = (const float*)d_in[2];
    const float* W_hh   = (const float*)d_in[3];
    const float* b_ih   = (const float*)d_in[4];
    const float* b_hh   = (const float*)d_in[5];
    const float* Wc     = (const float*)d_in[6];
    const float* bc     = (const float*)d_in[7];
    const float* phase  = (const float*)d_in[8];
    const float* te     = (const float*)d_in[9];
    const float* pe     = (const float*)d_in[10];
    const float* re_    = (const float*)d_in[11];
    const float* to     = (const float*)d_in[12];
    const float* po     = (const float*)d_in[13];
    const float* ro     = (const float*)d_in[14];
    const float* Rr     = (const float*)d_in[15];
    const float* Ri     = (const float*)d_in[16];
    float* out = (float*)d_out;

    static float* pG = nullptr;
    static float* pH = nullptr;
    static float* pZC = nullptr;
    if (!pG) {
        cudaGetSymbolAddress((void**)&pG, g_G);
        cudaGetSymbolAddress((void**)&pH, g_h);
        cudaGetSymbolAddress((void**)&pZC, g_zc);
        cudaFuncSetAttribute(gru_persist,
                             cudaFuncAttributeMaxDynamicSharedMemorySize, SMEM_BYTES);
    }
    float* pH0 = pH;
    float* pH1 = pH + NB * NE;

    // 0. Gate-interleave + tf32-round W_hh, permute b_hh
    permute_whh<<<(G3E * NE + 255) / 256, 256>>>(W_hh, b_hh);

    // 1. Token gate table: G = embed @ W_ih^T + b_ih  (V x 3E)
    gemm64_abT<<<dim3(G3E / 64, NV / 64), 256>>>(embed, W_ih, b_ih, pG, G3E, NE);

    // 2. h0 = 0 + barrier state reset
    init_kernel<<<(NB * NE + 255) / 256, 256>>>(pH0);

    // 3. Whole GRU recurrence in ONE persistent kernel (W resident in SMEM)
    gru_persist<<<dim3(16, 8), 256, SMEM_BYTES>>>(pH0, pH1, tokens);

    // 4. zc = h @ Wc^T + bc, then normalized complex psi (NT even -> h in pH0)
    gemm64_abT<<<dim3(2 * NM / 64, NB / 64), 256>>>(pH0, Wc, bc, pZC, 2 * NM, NE);
    psi_init_kernel<<<NB, 256>>>();

    // 5. 32 MZI layers, persistent row in SMEM
    mzi_kernel<<<NB, 512>>>(phase, te, pe, re_, to, po, ro);

    // 6. Readout complex GEMM + log|.|^2, then row logsumexp
    readout_kernel<<<dim3(NV / 64, NB / 64), 256>>>(Rr, Ri, out);
    lse_kernel<<<NB, 256>>>(out);
}